// round 1
// baseline (speedup 1.0000x reference)
#include <cuda_runtime.h>
#include <cstdint>

typedef unsigned long long ull;

// ---------------- problem constants ----------------
#define Bb 8
#define Nn 131072          // F*T = 256*512
#define Dd 40
#define Ss 4
#define P  48              // padded augmented row width (40 E + 4 V + 4 zero)
#define CELLS (P*P)        // 2304
#define CPB 37             // chunks per batch  -> 296 blocks = 2 per SM
#define CHUNK 3543         // ceil(131072/37)
#define RPW 448            // rows per warp (ceil(3543/8) rounded to 32)
#define NTILES 14          // 448/32
#define K2_BLOCKS 72       // ceil(8*2304/256)

// ---------------- device scratch (no allocs allowed) ----------------
__device__ __align__(16) float g_partials[(size_t)Bb * CPB * CELLS]; // 2.7 MB
__device__ float g_blocksums[K2_BLOCKS];

// ---------------- packed f32x2 helpers ----------------
#define FMA2(acc, a, b) asm("fma.rn.f32x2 %0, %1, %2, %0;" : "+l"(acc) : "l"(a), "l"(b))
#define ADD2(acc, x)    asm("add.rn.f32x2 %0, %0, %1;"     : "+l"(acc) : "l"(x))
#define PACK2(dst, lo, hi) asm("mov.b64 %0, {%1, %2};" : "=l"(dst) : "f"(lo), "f"(hi))

// ============================================================
// Kernel 1: per-(batch, chunk) partial Gram of augmented rows.
// One warp = one independent group. Each lane owns a 6(d) x 12(e)
// register tile of the 48x48 Gram, accumulated with fma.rn.f32x2.
// ============================================================
__global__ __launch_bounds__(256, 2)
void gram_kernel(const float* __restrict__ E, const float* __restrict__ V)
{
    __shared__ float sm[8 * 32 * P];   // 49152 B: 8 warps x 32 rows x 48 floats

    const int tid  = threadIdx.x;
    const int w    = tid >> 5;
    const int lane = tid & 31;
    const int ty   = lane >> 2;        // 0..7  -> d-rows ty*6 .. ty*6+5
    const int tx   = lane & 3;         // 0..3  -> e-cols tx*12 .. tx*12+11
    const int tyo  = ty * 6;
    const int txo  = tx * 12;

    const int b      = blockIdx.y;     // batch
    const int chunk  = blockIdx.x;     // 0..36
    const int n_end  = min(Nn, (chunk + 1) * CHUNK);
    const int warp_n0 = chunk * CHUNK + w * RPW;

    float* smw = &sm[w * 32 * P];

    ull acc[36];
#pragma unroll
    for (int k = 0; k < 36; k++) acc[k] = 0ull;   // bit pattern 0 == (0.f, 0.f)

    const size_t ebase = (size_t)b * Nn * Dd;
    const size_t vbase = (size_t)b * Nn * Ss;

    for (int t = 0; t < NTILES; t++) {
        const int n0 = warp_n0 + t * 32;

        __syncwarp();  // previous tile fully consumed before overwrite

        // ---- stage E: 32 rows x 40 floats = 320 contiguous float4 ----
        const float4* Ef4 = (const float4*)(E + ebase + (size_t)n0 * Dd);
#pragma unroll
        for (int i = 0; i < 10; i++) {
            const int f4   = lane + i * 32;     // 0..319
            const int elem = f4 * 4;
            const int r    = elem / 40;
            const int c    = elem - r * 40;
            float4 v = make_float4(0.f, 0.f, 0.f, 0.f);
            if (n0 + r < n_end) v = Ef4[f4];
            *(float4*)&smw[r * P + c] = v;
        }
        // ---- stage V + zero pad ----
        {
            const int r = lane;
            float4 v = make_float4(0.f, 0.f, 0.f, 0.f);
            if (n0 + r < n_end)
                v = *(const float4*)(V + vbase + (size_t)(n0 + r) * Ss);
            *(float4*)&smw[r * P + 40] = v;
            *(float4*)&smw[r * P + 44] = make_float4(0.f, 0.f, 0.f, 0.f);
        }
        __syncwarp();

        // ---- rank-1 accumulation over the 32 staged rows ----
#pragma unroll 4
        for (int r = 0; r < 32; r++) {
            const float* row = &smw[r * P];

            // e: 12 floats = 3x LDS.128, reinterpreted as 6 packed pairs
            ulonglong2 e01 = *(const ulonglong2*)&row[txo];
            ulonglong2 e23 = *(const ulonglong2*)&row[txo + 4];
            ulonglong2 e45 = *(const ulonglong2*)&row[txo + 8];
            ull e[6] = { e01.x, e01.y, e23.x, e23.y, e45.x, e45.y };

            // d: 6 floats = 3x LDS.64 (24B offsets -> 8B aligned only)
            float2 d01 = *(const float2*)&row[tyo];
            float2 d23 = *(const float2*)&row[tyo + 2];
            float2 d45 = *(const float2*)&row[tyo + 4];
            ull dp[6];
            PACK2(dp[0], d01.x, d01.x); PACK2(dp[1], d01.y, d01.y);
            PACK2(dp[2], d23.x, d23.x); PACK2(dp[3], d23.y, d23.y);
            PACK2(dp[4], d45.x, d45.x); PACK2(dp[5], d45.y, d45.y);

#pragma unroll
            for (int i = 0; i < 6; i++)
#pragma unroll
                for (int j = 0; j < 6; j++)
                    FMA2(acc[i * 6 + j], dp[i], e[j]);
        }
    }

    // ---- fold 8 warps -> warp 0 via smem tree (buffer reuse) ----
    ull* smu = (ull*)sm;
    for (int half = 4; half >= 1; half >>= 1) {
        __syncthreads();
        if (w >= half && w < 2 * half) {
            ull* dst = &smu[(size_t)((w - half) * 32 + lane) * 36];
#pragma unroll
            for (int k = 0; k < 36; k++) dst[k] = acc[k];
        }
        __syncthreads();
        if (w < half) {
            ull* src = &smu[(size_t)(w * 32 + lane) * 36];
#pragma unroll
            for (int k = 0; k < 36; k++) ADD2(acc[k], src[k]);
        }
    }

    if (w == 0) {
        float* out = &g_partials[(size_t)(b * CPB + chunk) * CELLS];
#pragma unroll
        for (int i = 0; i < 6; i++)
#pragma unroll
            for (int j = 0; j < 6; j++)
                *(ull*)&out[(tyo + i) * P + txo + 2 * j] = acc[i * 6 + j];
    }
}

// ============================================================
// Kernel 2: per-cell chunk reduction + weighted square, block-reduced.
// ============================================================
__global__ __launch_bounds__(256)
void reduce1_kernel()
{
    const int idx = blockIdx.x * 256 + threadIdx.x;
    float v = 0.f;
    if (idx < Bb * CELLS) {
        const int batch = idx / CELLS;
        const int cell  = idx - batch * CELLS;
        const int i = cell / P;
        const int j = cell - i * P;
        const float* p = &g_partials[(size_t)batch * CPB * CELLS + cell];
        float s = 0.f;
#pragma unroll 1
        for (int c = 0; c < CPB; c++) s += p[(size_t)c * CELLS];
        const float wgt = ((i < Dd) == (j < Dd)) ? 1.0f : -1.0f;
        v = wgt * s * s;
    }
    __shared__ float red[256];
    red[threadIdx.x] = v;
    __syncthreads();
#pragma unroll
    for (int h = 128; h > 0; h >>= 1) {
        if (threadIdx.x < h) red[threadIdx.x] += red[threadIdx.x + h];
        __syncthreads();
    }
    if (threadIdx.x == 0) g_blocksums[blockIdx.x] = red[0];
}

// ============================================================
// Kernel 3: final scalar.
// ============================================================
__global__ __launch_bounds__(128)
void reduce2_kernel(float* __restrict__ out)
{
    __shared__ float s[128];
    const int t = threadIdx.x;
    s[t] = (t < K2_BLOCKS) ? g_blocksums[t] : 0.f;
    __syncthreads();
#pragma unroll
    for (int h = 64; h > 0; h >>= 1) {
        if (t < h) s[t] += s[t + h];
        __syncthreads();
    }
    if (t == 0) out[0] = s[0] / (float)((size_t)Bb * Nn);   // / (b*n) = 1048576
}

// ============================================================
extern "C" void kernel_launch(void* const* d_in, const int* in_sizes, int n_in,
                              void* d_out, int out_size)
{
    const float* E = (const float*)d_in[0];
    const float* V = (const float*)d_in[1];
    // defensive: embeddings tensor (41.9M elems) is larger than assignments (4.2M)
    if (n_in >= 2 && in_sizes[0] < in_sizes[1]) {
        const float* tmp = E; E = V; V = tmp;
    }

    dim3 grid1(CPB, Bb);
    gram_kernel<<<grid1, 256>>>(E, V);
    reduce1_kernel<<<K2_BLOCKS, 256>>>();
    reduce2_kernel<<<1, 128>>>((float*)d_out);
}